// round 1
// baseline (speedup 1.0000x reference)
#include <cuda_runtime.h>

// Problem constants
#define BB 2
#define SS 2048
#define DD 1024
#define HH 16
#define HD 64

#define LOG2E 1.4426950408889634f
#define ATT_SCALE 0.125f   // 1/sqrt(64)

// Scratch (device globals; no allocation allowed)
__device__ float g_Q[BB * SS * DD];
__device__ float g_K[BB * SS * DD];
__device__ float g_V[BB * SS * DD];
__device__ float g_O[BB * SS * DD];

__device__ __forceinline__ float ex2(float x) {
    float y;
    asm("ex2.approx.ftz.f32 %0, %1;" : "=f"(y) : "f"(x));
    return y;
}

// ---------------------------------------------------------------------------
// NT GEMM core: C[m,n] = sum_k A[m,k] * W[n,k] + bias[n]
// Tile 128x128, BK=8, 256 threads, 8x8 micro-tile.
// ---------------------------------------------------------------------------
__device__ __forceinline__ void gemm_nt_core(const float* __restrict__ A,
                                             const float* __restrict__ W,
                                             const float* __restrict__ bias,
                                             float* __restrict__ C,
                                             int K, int N) {
    __shared__ float As[8][128];
    __shared__ float Ws[8][128];

    const int t  = threadIdx.x;
    const int bm = blockIdx.y * 128;
    const int bn = blockIdx.x * 128;
    const int lr = t >> 1;          // 0..127 row within tile
    const int ls = (t & 1) * 4;     // 0 or 4 (k-segment)
    const int tx = t & 15;
    const int ty = t >> 4;

    const float* Ap = A + (size_t)(bm + lr) * K + ls;
    const float* Wp = W + (size_t)(bn + lr) * K + ls;

    float acc[8][8];
#pragma unroll
    for (int i = 0; i < 8; i++)
#pragma unroll
        for (int j = 0; j < 8; j++) acc[i][j] = 0.f;

    for (int k0 = 0; k0 < K; k0 += 8) {
        float4 av = *(const float4*)(Ap + k0);
        float4 wv = *(const float4*)(Wp + k0);
        __syncthreads();   // previous iteration's readers done
        As[ls + 0][lr] = av.x; As[ls + 1][lr] = av.y;
        As[ls + 2][lr] = av.z; As[ls + 3][lr] = av.w;
        Ws[ls + 0][lr] = wv.x; Ws[ls + 1][lr] = wv.y;
        Ws[ls + 2][lr] = wv.z; Ws[ls + 3][lr] = wv.w;
        __syncthreads();
#pragma unroll
        for (int kk = 0; kk < 8; kk++) {
            float a[8], w[8];
            *(float4*)&a[0] = *(const float4*)&As[kk][ty * 8];
            *(float4*)&a[4] = *(const float4*)&As[kk][ty * 8 + 4];
            *(float4*)&w[0] = *(const float4*)&Ws[kk][tx * 8];
            *(float4*)&w[4] = *(const float4*)&Ws[kk][tx * 8 + 4];
#pragma unroll
            for (int i = 0; i < 8; i++)
#pragma unroll
                for (int j = 0; j < 8; j++) acc[i][j] += a[i] * w[j];
        }
    }

    float4 b0 = *(const float4*)(bias + bn + tx * 8);
    float4 b1 = *(const float4*)(bias + bn + tx * 8 + 4);
#pragma unroll
    for (int i = 0; i < 8; i++) {
        int row = bm + ty * 8 + i;
        float4 o0 = make_float4(acc[i][0] + b0.x, acc[i][1] + b0.y,
                                acc[i][2] + b0.z, acc[i][3] + b0.w);
        float4 o1 = make_float4(acc[i][4] + b1.x, acc[i][5] + b1.y,
                                acc[i][6] + b1.z, acc[i][7] + b1.w);
        *(float4*)(C + (size_t)row * N + bn + tx * 8)     = o0;
        *(float4*)(C + (size_t)row * N + bn + tx * 8 + 4) = o1;
    }
}

__global__ __launch_bounds__(256, 2) void gemm_qkv_kernel(
    const float* __restrict__ x,
    const float* __restrict__ Wq, const float* __restrict__ bq,
    const float* __restrict__ Wk, const float* __restrict__ bk,
    const float* __restrict__ Wv, const float* __restrict__ bv) {
    const float* W; const float* bia; float* C;
    if (blockIdx.z == 0)      { W = Wq; bia = bq; C = g_Q; }
    else if (blockIdx.z == 1) { W = Wk; bia = bk; C = g_K; }
    else                      { W = Wv; bia = bv; C = g_V; }
    gemm_nt_core(x, W, bia, C, DD, DD);
}

__global__ __launch_bounds__(256, 2) void gemm_o_kernel(
    const float* __restrict__ Wo, const float* __restrict__ bo,
    float* __restrict__ out) {
    gemm_nt_core(g_O, Wo, bo, out, DD, DD);
}

// ---------------------------------------------------------------------------
// RoPE over Q and K in-place. One thread per (b,s,d/2) pair.
// freqs: [S, HD/2, 2, 2] -> float4 (cos, -sin, sin, cos)
// ---------------------------------------------------------------------------
__global__ __launch_bounds__(256) void rope_kernel(const float* __restrict__ freqs) {
    int i = blockIdx.x * blockDim.x + threadIdx.x;   // 0 .. B*S*D/2-1
    int dh = i & 511;        // pair index within row (D/2 = 512)
    int p  = dh & 31;        // pair within head
    int bs = i >> 9;
    int s  = bs & (SS - 1);
    float4 f = *(const float4*)(freqs + (((size_t)s << 5) + p) * 4);
    float2* qp = (float2*)g_Q + i;
    float2* kp = (float2*)g_K + i;
    float2 qv = *qp;
    float2 kv = *kp;
    float2 qo, ko;
    qo.x = f.x * qv.x + f.y * qv.y;
    qo.y = f.z * qv.x + f.w * qv.y;
    ko.x = f.x * kv.x + f.y * kv.y;
    ko.y = f.z * kv.x + f.w * kv.y;
    *qp = qo;
    *kp = ko;
}

// ---------------------------------------------------------------------------
// Flash attention, fp32 SIMT.
// Grid: (S/128, B*H). 256 threads. Per iter: 64 k-rows.
// Smem: Qs[64][128] (d-major, pre-scaled), Ks[64][64] (d-major),
//       Vs[64][64] (row-major), Ps[64][132] (j-major, i contiguous).
// Thread (ty=t/16, tx=t%16): rows i = ty*8..+7, cols j/d = tx*4..+3.
// ---------------------------------------------------------------------------
#define PS_LD 132
#define ATT_SMEM_FLOATS (64 * 128 + 64 * 64 + 64 * 64 + 64 * PS_LD)

__global__ __launch_bounds__(256, 2) void attn_kernel() {
    extern __shared__ float sm[];
    float* Qs = sm;                       // 64 x 128
    float* Ks = Qs + 64 * 128;            // 64 x 64
    float* Vs = Ks + 64 * 64;             // 64 x 64
    float* Ps = Vs + 64 * 64;             // 64 x PS_LD

    const int t  = threadIdx.x;
    const int tx = t & 15;
    const int ty = t >> 4;
    const int qb = blockIdx.x;            // q tile
    const int bh = blockIdx.y;
    const int b  = bh >> 4;
    const int h  = bh & 15;

    const float* Qg = g_Q + ((size_t)b * SS + qb * 128) * DD + h * HD;
    const float* Kg = g_K + (size_t)b * SS * DD + h * HD;
    const float* Vg = g_V + (size_t)b * SS * DD + h * HD;

    // Load Q tile transposed (Qs[d][i]) and pre-scaled by scale*log2(e).
    {
        const float qs = ATT_SCALE * LOG2E;
#pragma unroll
        for (int r = 0; r < 8; r++) {
            int idx = r * 256 + t;
            int row = idx & 127;          // lane-consecutive rows -> conflict-free STS
            int cs  = idx >> 7;           // 0..15
            float4 v = *(const float4*)(Qg + (size_t)row * DD + cs * 4);
            Qs[(cs * 4 + 0) * 128 + row] = v.x * qs;
            Qs[(cs * 4 + 1) * 128 + row] = v.y * qs;
            Qs[(cs * 4 + 2) * 128 + row] = v.z * qs;
            Qs[(cs * 4 + 3) * 128 + row] = v.w * qs;
        }
    }

    float o[8][4];
    float m[8], l[8];
#pragma unroll
    for (int ii = 0; ii < 8; ii++) {
        m[ii] = -1e30f;
        l[ii] = 0.f;
#pragma unroll
        for (int jj = 0; jj < 4; jj++) o[ii][jj] = 0.f;
    }

    for (int kb = 0; kb < SS / 64; kb++) {
        // Prefetch K (transposed mapping) + V (row mapping) into registers.
        float4 kv[4], vv[4];
        int krow[4], kcs[4], vrow[4], vcs[4];
#pragma unroll
        for (int r = 0; r < 4; r++) {
            int idx = r * 256 + t;
            krow[r] = idx & 63;
            kcs[r]  = idx >> 6;
            kv[r] = *(const float4*)(Kg + (size_t)(kb * 64 + krow[r]) * DD + kcs[r] * 4);
            vrow[r] = idx >> 4;
            vcs[r]  = idx & 15;
            vv[r] = *(const float4*)(Vg + (size_t)(kb * 64 + vrow[r]) * DD + vcs[r] * 4);
        }
        __syncthreads();   // previous iteration fully consumed smem
#pragma unroll
        for (int r = 0; r < 4; r++) {
            Ks[(kcs[r] * 4 + 0) * 64 + krow[r]] = kv[r].x;
            Ks[(kcs[r] * 4 + 1) * 64 + krow[r]] = kv[r].y;
            Ks[(kcs[r] * 4 + 2) * 64 + krow[r]] = kv[r].z;
            Ks[(kcs[r] * 4 + 3) * 64 + krow[r]] = kv[r].w;
            *(float4*)&Vs[vrow[r] * 64 + vcs[r] * 4] = vv[r];
        }
        __syncthreads();

        // S = Q K^T (log2-scaled)
        float s[8][4];
#pragma unroll
        for (int ii = 0; ii < 8; ii++)
#pragma unroll
            for (int jj = 0; jj < 4; jj++) s[ii][jj] = 0.f;
#pragma unroll
        for (int d = 0; d < 64; d++) {
            float a[8], kk[4];
            *(float4*)&a[0]  = *(const float4*)&Qs[d * 128 + ty * 8];
            *(float4*)&a[4]  = *(const float4*)&Qs[d * 128 + ty * 8 + 4];
            *(float4*)&kk[0] = *(const float4*)&Ks[d * 64 + tx * 4];
#pragma unroll
            for (int ii = 0; ii < 8; ii++)
#pragma unroll
                for (int jj = 0; jj < 4; jj++) s[ii][jj] += a[ii] * kk[jj];
        }

        // Online softmax update
#pragma unroll
        for (int ii = 0; ii < 8; ii++) {
            float rm = fmaxf(fmaxf(s[ii][0], s[ii][1]), fmaxf(s[ii][2], s[ii][3]));
            rm = fmaxf(rm, __shfl_xor_sync(0xffffffffu, rm, 1));
            rm = fmaxf(rm, __shfl_xor_sync(0xffffffffu, rm, 2));
            rm = fmaxf(rm, __shfl_xor_sync(0xffffffffu, rm, 4));
            rm = fmaxf(rm, __shfl_xor_sync(0xffffffffu, rm, 8));
            float mn    = fmaxf(m[ii], rm);
            float alpha = ex2(m[ii] - mn);
            m[ii] = mn;
            float ps = 0.f;
#pragma unroll
            for (int jj = 0; jj < 4; jj++) {
                float p = ex2(s[ii][jj] - mn);
                s[ii][jj] = p;
                ps += p;
            }
            l[ii] = l[ii] * alpha + ps;
#pragma unroll
            for (int jj = 0; jj < 4; jj++) o[ii][jj] *= alpha;
        }

        // P -> smem, transposed: Ps[j][i]
#pragma unroll
        for (int jj = 0; jj < 4; jj++) {
            int j = tx * 4 + jj;
            float4 p0 = make_float4(s[0][jj], s[1][jj], s[2][jj], s[3][jj]);
            float4 p1 = make_float4(s[4][jj], s[5][jj], s[6][jj], s[7][jj]);
            *(float4*)&Ps[j * PS_LD + ty * 8]     = p0;
            *(float4*)&Ps[j * PS_LD + ty * 8 + 4] = p1;
        }
        __syncthreads();

        // O += P V
#pragma unroll
        for (int j = 0; j < 64; j++) {
            float pv[8], vr[4];
            *(float4*)&pv[0] = *(const float4*)&Ps[j * PS_LD + ty * 8];
            *(float4*)&pv[4] = *(const float4*)&Ps[j * PS_LD + ty * 8 + 4];
            *(float4*)&vr[0] = *(const float4*)&Vs[j * 64 + tx * 4];
#pragma unroll
            for (int ii = 0; ii < 8; ii++)
#pragma unroll
                for (int jj = 0; jj < 4; jj++) o[ii][jj] += pv[ii] * vr[jj];
        }
    }

    // Epilogue: reduce l across tx, normalize, write to g_O ([B,S,D] layout)
    float* Og = g_O + ((size_t)b * SS + qb * 128) * DD + h * HD;
#pragma unroll
    for (int ii = 0; ii < 8; ii++) {
        float ls = l[ii];
        ls += __shfl_xor_sync(0xffffffffu, ls, 1);
        ls += __shfl_xor_sync(0xffffffffu, ls, 2);
        ls += __shfl_xor_sync(0xffffffffu, ls, 4);
        ls += __shfl_xor_sync(0xffffffffu, ls, 8);
        float inv = 1.f / ls;
        float4 outv = make_float4(o[ii][0] * inv, o[ii][1] * inv,
                                  o[ii][2] * inv, o[ii][3] * inv);
        *(float4*)(Og + (size_t)(ty * 8 + ii) * DD + tx * 4) = outv;
    }
}

// ---------------------------------------------------------------------------
extern "C" void kernel_launch(void* const* d_in, const int* in_sizes, int n_in,
                              void* d_out, int out_size) {
    const float* x     = (const float*)d_in[0];
    const float* freqs = (const float*)d_in[1];
    const float* Wq    = (const float*)d_in[2];
    const float* bq    = (const float*)d_in[3];
    const float* Wk    = (const float*)d_in[4];
    const float* bk    = (const float*)d_in[5];
    const float* Wv    = (const float*)d_in[6];
    const float* bv    = (const float*)d_in[7];
    const float* Wo    = (const float*)d_in[8];
    const float* bo    = (const float*)d_in[9];
    float* out = (float*)d_out;

    static const size_t attn_smem = ATT_SMEM_FLOATS * sizeof(float);
    cudaFuncSetAttribute(attn_kernel, cudaFuncAttributeMaxDynamicSharedMemorySize,
                         (int)attn_smem);

    // 1) QKV projections (3 GEMMs fused in one grid via z)
    gemm_qkv_kernel<<<dim3(DD / 128, (BB * SS) / 128, 3), 256>>>(
        x, Wq, bq, Wk, bk, Wv, bv);

    // 2) RoPE on Q and K
    rope_kernel<<<(BB * SS * DD / 2) / 256, 256>>>(freqs);

    // 3) Flash attention
    attn_kernel<<<dim3(SS / 128, BB * HH), 256, attn_smem>>>();

    // 4) Output projection
    gemm_o_kernel<<<dim3(DD / 128, (BB * SS) / 128, 1), 256>>>(Wo, bo, out);
}

// round 2
// speedup vs baseline: 1.5793x; 1.5793x over previous
#include <cuda_runtime.h>

// Problem constants
#define BB 2
#define SS 2048
#define DD 1024
#define HH 16
#define HD 64

#define LOG2E 1.4426950408889634f
#define ATT_SCALE 0.125f   // 1/sqrt(64)

// Scratch (device globals; no allocation allowed)
__device__ float g_Q[BB * SS * DD];
__device__ float g_K[BB * SS * DD];
__device__ float g_V[BB * SS * DD];
__device__ float g_O[BB * SS * DD];

__device__ __forceinline__ float ex2(float x) {
    float y;
    asm("ex2.approx.ftz.f32 %0, %1;" : "=f"(y) : "f"(x));
    return y;
}

__device__ __forceinline__ float tf32r(float x) {
    float r;
    asm("cvt.rna.tf32.f32 %0, %1;" : "=f"(r) : "f"(x));
    return r;
}

__device__ __forceinline__ void split2(float x, float& h, float& l) {
    h = tf32r(x);
    l = tf32r(x - h);
}

// m16n8k8 tf32 mma, D accumulates in place.
__device__ __forceinline__ void mma8(float4& d, const unsigned* a, const unsigned* b) {
    asm volatile(
        "mma.sync.aligned.m16n8k8.row.col.f32.tf32.tf32.f32 "
        "{%0,%1,%2,%3}, {%4,%5,%6,%7}, {%8,%9}, {%0,%1,%2,%3};"
        : "+f"(d.x), "+f"(d.y), "+f"(d.z), "+f"(d.w)
        : "r"(a[0]), "r"(a[1]), "r"(a[2]), "r"(a[3]), "r"(b[0]), "r"(b[1]));
}

// ---------------------------------------------------------------------------
// NT GEMM, tf32 tensor cores with 3xTF32 split: C = A @ W^T + bias
// Tile 128x128, BK=32, 256 threads (8 warps, 2x4), warp tile 64x32.
// ---------------------------------------------------------------------------
#define GLD 36
#define GEMM_SMEM_FLOATS (4 * 128 * GLD)

__device__ __forceinline__ void gemm_tc_core(const float* __restrict__ A,
                                             const float* __restrict__ W,
                                             const float* __restrict__ bias,
                                             float* __restrict__ C) {
    extern __shared__ float gs[];
    float* Ah = gs;
    float* Al = Ah + 128 * GLD;
    float* Wh = Al + 128 * GLD;
    float* Wl = Wh + 128 * GLD;

    const int t = threadIdx.x;
    const int lane = t & 31, w = t >> 5;
    const int g = lane >> 2, qd = lane & 3;
    const int wm = (w >> 2) * 64;
    const int wn = (w & 3) * 32;
    const int bm = blockIdx.y * 128, bn = blockIdx.x * 128;
    const int lrow = t >> 3;
    const int lq = (t & 7) * 4;

    float4 cfr[4][4];
#pragma unroll
    for (int i = 0; i < 4; i++)
#pragma unroll
        for (int j = 0; j < 4; j++) cfr[i][j] = make_float4(0.f, 0.f, 0.f, 0.f);

    const float* Ag = A + (size_t)bm * DD;
    const float* Wg = W + (size_t)bn * DD;

    for (int k0 = 0; k0 < DD; k0 += 32) {
        float4 av[4], wv[4];
#pragma unroll
        for (int r = 0; r < 4; r++) {
            av[r] = *(const float4*)(Ag + (size_t)(r * 32 + lrow) * DD + k0 + lq);
            wv[r] = *(const float4*)(Wg + (size_t)(r * 32 + lrow) * DD + k0 + lq);
        }
        __syncthreads();
#pragma unroll
        for (int r = 0; r < 4; r++) {
            int base = (r * 32 + lrow) * GLD + lq;
            float4 h, l;
            split2(av[r].x, h.x, l.x); split2(av[r].y, h.y, l.y);
            split2(av[r].z, h.z, l.z); split2(av[r].w, h.w, l.w);
            *(float4*)&Ah[base] = h;
            *(float4*)&Al[base] = l;
            split2(wv[r].x, h.x, l.x); split2(wv[r].y, h.y, l.y);
            split2(wv[r].z, h.z, l.z); split2(wv[r].w, h.w, l.w);
            *(float4*)&Wh[base] = h;
            *(float4*)&Wl[base] = l;
        }
        __syncthreads();
#pragma unroll
        for (int ks = 0; ks < 4; ks++) {
            unsigned ah[4][4], al[4][4], bh[4][2], bl[4][2];
#pragma unroll
            for (int mt = 0; mt < 4; mt++) {
                int ba = (wm + mt * 16 + g) * GLD + ks * 8 + qd;
                ah[mt][0] = __float_as_uint(Ah[ba]);
                ah[mt][1] = __float_as_uint(Ah[ba + 8 * GLD]);
                ah[mt][2] = __float_as_uint(Ah[ba + 4]);
                ah[mt][3] = __float_as_uint(Ah[ba + 8 * GLD + 4]);
                al[mt][0] = __float_as_uint(Al[ba]);
                al[mt][1] = __float_as_uint(Al[ba + 8 * GLD]);
                al[mt][2] = __float_as_uint(Al[ba + 4]);
                al[mt][3] = __float_as_uint(Al[ba + 8 * GLD + 4]);
            }
#pragma unroll
            for (int nt = 0; nt < 4; nt++) {
                int bb = (wn + nt * 8 + g) * GLD + ks * 8 + qd;
                bh[nt][0] = __float_as_uint(Wh[bb]);
                bh[nt][1] = __float_as_uint(Wh[bb + 4]);
                bl[nt][0] = __float_as_uint(Wl[bb]);
                bl[nt][1] = __float_as_uint(Wl[bb + 4]);
            }
#pragma unroll
            for (int mt = 0; mt < 4; mt++)
#pragma unroll
                for (int nt = 0; nt < 4; nt++) {
                    mma8(cfr[mt][nt], ah[mt], bh[nt]);
                    mma8(cfr[mt][nt], ah[mt], bl[nt]);
                    mma8(cfr[mt][nt], al[mt], bh[nt]);
                }
        }
    }

#pragma unroll
    for (int mt = 0; mt < 4; mt++) {
        int r0 = bm + wm + mt * 16 + g;
#pragma unroll
        for (int nt = 0; nt < 4; nt++) {
            int col = bn + wn + nt * 8 + qd * 2;
            float2 bb = *(const float2*)(bias + col);
            float2 v0 = make_float2(cfr[mt][nt].x + bb.x, cfr[mt][nt].y + bb.y);
            float2 v1 = make_float2(cfr[mt][nt].z + bb.x, cfr[mt][nt].w + bb.y);
            *(float2*)(C + (size_t)r0 * DD + col) = v0;
            *(float2*)(C + (size_t)(r0 + 8) * DD + col) = v1;
        }
    }
}

__global__ __launch_bounds__(256, 2) void gemm_qkv_kernel(
    const float* __restrict__ x,
    const float* __restrict__ Wq, const float* __restrict__ bq,
    const float* __restrict__ Wk, const float* __restrict__ bk,
    const float* __restrict__ Wv, const float* __restrict__ bv) {
    const float* W; const float* bia; float* C;
    if (blockIdx.z == 0)      { W = Wq; bia = bq; C = g_Q; }
    else if (blockIdx.z == 1) { W = Wk; bia = bk; C = g_K; }
    else                      { W = Wv; bia = bv; C = g_V; }
    gemm_tc_core(x, W, bia, C);
}

__global__ __launch_bounds__(256, 2) void gemm_o_kernel(
    const float* __restrict__ Wo, const float* __restrict__ bo,
    float* __restrict__ out) {
    gemm_tc_core(g_O, Wo, bo, out);
}

// ---------------------------------------------------------------------------
// RoPE over Q and K in-place (unchanged from round 1).
// ---------------------------------------------------------------------------
__global__ __launch_bounds__(256) void rope_kernel(const float* __restrict__ freqs) {
    int i = blockIdx.x * blockDim.x + threadIdx.x;
    int dh = i & 511;
    int p  = dh & 31;
    int bs = i >> 9;
    int s  = bs & (SS - 1);
    float4 f = *(const float4*)(freqs + (((size_t)s << 5) + p) * 4);
    float2* qp = (float2*)g_Q + i;
    float2* kp = (float2*)g_K + i;
    float2 qv = *qp;
    float2 kv = *kp;
    float2 qo, ko;
    qo.x = f.x * qv.x + f.y * qv.y;
    qo.y = f.z * qv.x + f.w * qv.y;
    ko.x = f.x * kv.x + f.y * kv.y;
    ko.y = f.z * kv.x + f.w * kv.y;
    *qp = qo;
    *kp = ko;
}

// ---------------------------------------------------------------------------
// Flash attention, tf32 tensor cores with 3xTF32 split.
// Grid (16, 32), 256 threads / 8 warps; warp owns 16 q-rows.
// Smem (floats): Kh/Kl [64][68], Vh/Vl [64][72], Ph/Pl [128][68].
// Ph/Pl double as Q-staging before the main loop.
// ---------------------------------------------------------------------------
#define KLD 68
#define VLD 72
#define PLD 68
#define ATT_SMEM_FLOATS (2 * 64 * KLD + 2 * 64 * VLD + 2 * 128 * PLD)

__global__ __launch_bounds__(256, 1) void attn_tc_kernel() {
    extern __shared__ float sm[];
    float* Kh = sm;
    float* Kl = Kh + 64 * KLD;
    float* Vh = Kl + 64 * KLD;
    float* Vl = Vh + 64 * VLD;
    float* Ph = Vl + 64 * VLD;
    float* Pl = Ph + 128 * PLD;

    const int t = threadIdx.x;
    const int lane = t & 31, w = t >> 5;
    const int g = lane >> 2, qd = lane & 3;
    const int qb = blockIdx.x, bh = blockIdx.y;
    const int b = bh >> 4, h = bh & 15;

    const float* Qg = g_Q + ((size_t)b * SS + qb * 128) * DD + h * HD;
    const float* Kg = g_K + (size_t)b * SS * DD + h * HD;
    const float* Vg = g_V + (size_t)b * SS * DD + h * HD;

    // Stage Q (prescaled by scale*log2e) into Ph/Pl as hi/lo tf32.
    const float qs = ATT_SCALE * LOG2E;
#pragma unroll
    for (int r = 0; r < 8; r++) {
        int idx = r * 256 + t;
        int row = idx >> 4, cq = (idx & 15) * 4;
        float4 v = *(const float4*)(Qg + (size_t)row * DD + cq);
        float4 hh, ll;
        split2(v.x * qs, hh.x, ll.x); split2(v.y * qs, hh.y, ll.y);
        split2(v.z * qs, hh.z, ll.z); split2(v.w * qs, hh.w, ll.w);
        *(float4*)&Ph[row * PLD + cq] = hh;
        *(float4*)&Pl[row * PLD + cq] = ll;
    }
    __syncthreads();

    // Q fragments (A, m16k8 x 8 k-steps), held in registers for whole kernel.
    unsigned qh[8][4], ql[8][4];
#pragma unroll
    for (int ks = 0; ks < 8; ks++) {
        int ba = (w * 16 + g) * PLD + ks * 8 + qd;
        qh[ks][0] = __float_as_uint(Ph[ba]);
        qh[ks][1] = __float_as_uint(Ph[ba + 8 * PLD]);
        qh[ks][2] = __float_as_uint(Ph[ba + 4]);
        qh[ks][3] = __float_as_uint(Ph[ba + 8 * PLD + 4]);
        ql[ks][0] = __float_as_uint(Pl[ba]);
        ql[ks][1] = __float_as_uint(Pl[ba + 8 * PLD]);
        ql[ks][2] = __float_as_uint(Pl[ba + 4]);
        ql[ks][3] = __float_as_uint(Pl[ba + 8 * PLD + 4]);
    }

    float4 ofr[8];
#pragma unroll
    for (int nt = 0; nt < 8; nt++) ofr[nt] = make_float4(0.f, 0.f, 0.f, 0.f);
    float m0 = -1e30f, m1 = -1e30f, l0 = 0.f, l1 = 0.f;

    for (int kb = 0; kb < SS / 64; kb++) {
        // Prefetch K/V block (coalesced)
        float4 kv[4], vv[4];
#pragma unroll
        for (int r = 0; r < 4; r++) {
            int idx = r * 256 + t;
            int row = idx >> 4, cq = (idx & 15) * 4;
            kv[r] = *(const float4*)(Kg + (size_t)(kb * 64 + row) * DD + cq);
            vv[r] = *(const float4*)(Vg + (size_t)(kb * 64 + row) * DD + cq);
        }
        __syncthreads();   // prev iter's smem reads (incl. P) complete
#pragma unroll
        for (int r = 0; r < 4; r++) {
            int idx = r * 256 + t;
            int row = idx >> 4, cq = (idx & 15) * 4;
            float4 h, l;
            split2(kv[r].x, h.x, l.x); split2(kv[r].y, h.y, l.y);
            split2(kv[r].z, h.z, l.z); split2(kv[r].w, h.w, l.w);
            *(float4*)&Kh[row * KLD + cq] = h;
            *(float4*)&Kl[row * KLD + cq] = l;
            split2(vv[r].x, h.x, l.x); split2(vv[r].y, h.y, l.y);
            split2(vv[r].z, h.z, l.z); split2(vv[r].w, h.w, l.w);
            *(float4*)&Vh[row * VLD + cq] = h;
            *(float4*)&Vl[row * VLD + cq] = l;
        }
        __syncthreads();

        // S = Q K^T  (log2-domain, pre-scaled)
        float4 sfr[8];
#pragma unroll
        for (int nt = 0; nt < 8; nt++) sfr[nt] = make_float4(0.f, 0.f, 0.f, 0.f);
#pragma unroll
        for (int ks = 0; ks < 8; ks++) {
#pragma unroll
            for (int nt = 0; nt < 8; nt++) {
                int bb = (nt * 8 + g) * KLD + ks * 8 + qd;
                unsigned kbh[2] = { __float_as_uint(Kh[bb]), __float_as_uint(Kh[bb + 4]) };
                unsigned kbl[2] = { __float_as_uint(Kl[bb]), __float_as_uint(Kl[bb + 4]) };
                mma8(sfr[nt], qh[ks], kbh);
                mma8(sfr[nt], qh[ks], kbl);
                mma8(sfr[nt], ql[ks], kbh);
            }
        }

        // Online softmax (rows g and g+8; reduce across quad lanes)
        float rm0 = -1e30f, rm1 = -1e30f;
#pragma unroll
        for (int nt = 0; nt < 8; nt++) {
            rm0 = fmaxf(rm0, fmaxf(sfr[nt].x, sfr[nt].y));
            rm1 = fmaxf(rm1, fmaxf(sfr[nt].z, sfr[nt].w));
        }
        rm0 = fmaxf(rm0, __shfl_xor_sync(0xffffffffu, rm0, 1));
        rm0 = fmaxf(rm0, __shfl_xor_sync(0xffffffffu, rm0, 2));
        rm1 = fmaxf(rm1, __shfl_xor_sync(0xffffffffu, rm1, 1));
        rm1 = fmaxf(rm1, __shfl_xor_sync(0xffffffffu, rm1, 2));
        float mn0 = fmaxf(m0, rm0), mn1 = fmaxf(m1, rm1);
        float a0 = ex2(m0 - mn0), a1 = ex2(m1 - mn1);
        m0 = mn0; m1 = mn1;
        float ps0 = 0.f, ps1 = 0.f;
        const int pr0 = (w * 16 + g) * PLD;
        const int pr1 = pr0 + 8 * PLD;
#pragma unroll
        for (int nt = 0; nt < 8; nt++) {
            float p0 = ex2(sfr[nt].x - mn0);
            float p1 = ex2(sfr[nt].y - mn0);
            float p2 = ex2(sfr[nt].z - mn1);
            float p3 = ex2(sfr[nt].w - mn1);
            ps0 += p0 + p1;
            ps1 += p2 + p3;
            float h0, l0_, h1, l1_, h2, l2_, h3, l3_;
            split2(p0, h0, l0_); split2(p1, h1, l1_);
            split2(p2, h2, l2_); split2(p3, h3, l3_);
            int col = nt * 8 + qd * 2;
            *(float2*)&Ph[pr0 + col] = make_float2(h0, h1);
            *(float2*)&Pl[pr0 + col] = make_float2(l0_, l1_);
            *(float2*)&Ph[pr1 + col] = make_float2(h2, h3);
            *(float2*)&Pl[pr1 + col] = make_float2(l2_, l3_);
        }
        l0 = l0 * a0 + ps0;
        l1 = l1 * a1 + ps1;
#pragma unroll
        for (int nt = 0; nt < 8; nt++) {
            ofr[nt].x *= a0; ofr[nt].y *= a0;
            ofr[nt].z *= a1; ofr[nt].w *= a1;
        }
        __syncwarp();   // P visible to all lanes of this warp

        // O += P V
#pragma unroll
        for (int ks = 0; ks < 8; ks++) {
            unsigned pah[4], pal[4];
            int ba = (w * 16 + g) * PLD + ks * 8 + qd;
            pah[0] = __float_as_uint(Ph[ba]);
            pah[1] = __float_as_uint(Ph[ba + 8 * PLD]);
            pah[2] = __float_as_uint(Ph[ba + 4]);
            pah[3] = __float_as_uint(Ph[ba + 8 * PLD + 4]);
            pal[0] = __float_as_uint(Pl[ba]);
            pal[1] = __float_as_uint(Pl[ba + 8 * PLD]);
            pal[2] = __float_as_uint(Pl[ba + 4]);
            pal[3] = __float_as_uint(Pl[ba + 8 * PLD + 4]);
#pragma unroll
            for (int nt = 0; nt < 8; nt++) {
                int bb = (ks * 8 + qd) * VLD + nt * 8 + g;
                unsigned vbh[2] = { __float_as_uint(Vh[bb]), __float_as_uint(Vh[bb + 4 * VLD]) };
                unsigned vbl[2] = { __float_as_uint(Vl[bb]), __float_as_uint(Vl[bb + 4 * VLD]) };
                mma8(ofr[nt], pah, vbh);
                mma8(ofr[nt], pah, vbl);
                mma8(ofr[nt], pal, vbh);
            }
        }
    }

    // Epilogue: reduce l over quad, normalize, store.
    l0 += __shfl_xor_sync(0xffffffffu, l0, 1);
    l0 += __shfl_xor_sync(0xffffffffu, l0, 2);
    l1 += __shfl_xor_sync(0xffffffffu, l1, 1);
    l1 += __shfl_xor_sync(0xffffffffu, l1, 2);
    float i0 = 1.f / l0, i1 = 1.f / l1;
    float* Og = g_O + ((size_t)b * SS + qb * 128 + w * 16) * DD + h * HD;
#pragma unroll
    for (int nt = 0; nt < 8; nt++) {
        int col = nt * 8 + qd * 2;
        *(float2*)(Og + (size_t)g * DD + col) =
            make_float2(ofr[nt].x * i0, ofr[nt].y * i0);
        *(float2*)(Og + (size_t)(g + 8) * DD + col) =
            make_float2(ofr[nt].z * i1, ofr[nt].w * i1);
    }
}

// ---------------------------------------------------------------------------
extern "C" void kernel_launch(void* const* d_in, const int* in_sizes, int n_in,
                              void* d_out, int out_size) {
    const float* x     = (const float*)d_in[0];
    const float* freqs = (const float*)d_in[1];
    const float* Wq    = (const float*)d_in[2];
    const float* bq    = (const float*)d_in[3];
    const float* Wk    = (const float*)d_in[4];
    const float* bk    = (const float*)d_in[5];
    const float* Wv    = (const float*)d_in[6];
    const float* bv    = (const float*)d_in[7];
    const float* Wo    = (const float*)d_in[8];
    const float* bo    = (const float*)d_in[9];
    float* out = (float*)d_out;

    const size_t gemm_smem = GEMM_SMEM_FLOATS * sizeof(float);   // 73728 B
    const size_t attn_smem = ATT_SMEM_FLOATS * sizeof(float);    // 141312 B
    cudaFuncSetAttribute(gemm_qkv_kernel, cudaFuncAttributeMaxDynamicSharedMemorySize,
                         (int)gemm_smem);
    cudaFuncSetAttribute(gemm_o_kernel, cudaFuncAttributeMaxDynamicSharedMemorySize,
                         (int)gemm_smem);
    cudaFuncSetAttribute(attn_tc_kernel, cudaFuncAttributeMaxDynamicSharedMemorySize,
                         (int)attn_smem);

    // 1) QKV projections
    gemm_qkv_kernel<<<dim3(DD / 128, (BB * SS) / 128, 3), 256, gemm_smem>>>(
        x, Wq, bq, Wk, bk, Wv, bv);

    // 2) RoPE on Q and K
    rope_kernel<<<(BB * SS * DD / 2) / 256, 256>>>(freqs);

    // 3) Flash attention (tf32 tensor cores)
    attn_tc_kernel<<<dim3(SS / 128, BB * HH), 256, attn_smem>>>();

    // 4) Output projection
    gemm_o_kernel<<<dim3(DD / 128, (BB * SS) / 128, 1), 256, gemm_smem>>>(Wo, bo, out);
}

// round 3
// speedup vs baseline: 2.7894x; 1.7663x over previous
#include <cuda_runtime.h>
#include <cuda_bf16.h>

// Problem constants
#define BB 2
#define SS 2048
#define DD 1024
#define HH 16
#define HD 64

#define LOG2E 1.4426950408889634f
#define ATT_SCALE 0.125f   // 1/sqrt(64)

// Scratch (device globals; no allocation allowed)
__device__ float g_Q[BB * SS * DD];
__device__ float g_K[BB * SS * DD];
__device__ float g_V[BB * SS * DD];
__device__ float g_O[BB * SS * DD];

__device__ __forceinline__ float ex2(float x) {
    float y;
    asm("ex2.approx.ftz.f32 %0, %1;" : "=f"(y) : "f"(x));
    return y;
}

// Pack two floats into bf16x2 word: a -> low half, b -> high half.
__device__ __forceinline__ unsigned pk2(float a, float b) {
    unsigned r;
    asm("cvt.rn.bf16x2.f32 %0, %2, %1;" : "=r"(r) : "f"(a), "f"(b));
    return r;
}

// Split a pair (a,b) into hi bf16x2 word and lo bf16x2 word.
__device__ __forceinline__ void split_pair(float a, float b, unsigned& wh, unsigned& wl) {
    wh = pk2(a, b);
    float ha = __uint_as_float(wh << 16);
    float hb = __uint_as_float(wh & 0xffff0000u);
    wl = pk2(a - ha, b - hb);
}

// m16n8k16 bf16 mma, D accumulates in place.
__device__ __forceinline__ void mma16(float4& d, const unsigned* a, const unsigned* b) {
    asm volatile(
        "mma.sync.aligned.m16n8k16.row.col.f32.bf16.bf16.f32 "
        "{%0,%1,%2,%3}, {%4,%5,%6,%7}, {%8,%9}, {%0,%1,%2,%3};"
        : "+f"(d.x), "+f"(d.y), "+f"(d.z), "+f"(d.w)
        : "r"(a[0]), "r"(a[1]), "r"(a[2]), "r"(a[3]), "r"(b[0]), "r"(b[1]));
}

// ---------------------------------------------------------------------------
// NT GEMM, bf16 tensor cores with 3xBF16 split: C = A @ W^T + bias
// Tile 128x128, BK=32 (16 k-pairs), 256 threads (8 warps, 2x4), warp 64x32.
// Smem words (bf16x2 pairs along k): Ah/Al/Wh/Wl [128][GLD].
// ---------------------------------------------------------------------------
#define GLD 20
#define GEMM_SMEM_WORDS (4 * 128 * GLD)

__device__ __forceinline__ void gemm_tc_core(const float* __restrict__ A,
                                             const float* __restrict__ W,
                                             const float* __restrict__ bias,
                                             float* __restrict__ C) {
    extern __shared__ unsigned gsu[];
    unsigned* Ah = gsu;
    unsigned* Al = Ah + 128 * GLD;
    unsigned* Wh = Al + 128 * GLD;
    unsigned* Wl = Wh + 128 * GLD;

    const int t = threadIdx.x;
    const int lane = t & 31, w = t >> 5;
    const int g = lane >> 2, qd = lane & 3;
    const int wm = (w >> 2) * 64;
    const int wn = (w & 3) * 32;
    const int bm = blockIdx.y * 128, bn = blockIdx.x * 128;

    float4 cfr[4][4];
#pragma unroll
    for (int i = 0; i < 4; i++)
#pragma unroll
        for (int j = 0; j < 4; j++) cfr[i][j] = make_float4(0.f, 0.f, 0.f, 0.f);

    const float* Ag = A + (size_t)bm * DD;
    const float* Wg = W + (size_t)bn * DD;

    for (int k0 = 0; k0 < DD; k0 += 32) {
        // 128 rows x 8 float4-chunks, 4 chunks per thread
        float4 av[4], wv[4];
#pragma unroll
        for (int r = 0; r < 4; r++) {
            int idx = r * 256 + t;
            int row = idx >> 3, ch = idx & 7;
            av[r] = *(const float4*)(Ag + (size_t)row * DD + k0 + ch * 4);
            wv[r] = *(const float4*)(Wg + (size_t)row * DD + k0 + ch * 4);
        }
        __syncthreads();
#pragma unroll
        for (int r = 0; r < 4; r++) {
            int idx = r * 256 + t;
            int row = idx >> 3, ch = idx & 7;
            int base = row * GLD + ch * 2;
            unsigned h0, l0, h1, l1;
            split_pair(av[r].x, av[r].y, h0, l0);
            split_pair(av[r].z, av[r].w, h1, l1);
            *(uint2*)&Ah[base] = make_uint2(h0, h1);
            *(uint2*)&Al[base] = make_uint2(l0, l1);
            split_pair(wv[r].x, wv[r].y, h0, l0);
            split_pair(wv[r].z, wv[r].w, h1, l1);
            *(uint2*)&Wh[base] = make_uint2(h0, h1);
            *(uint2*)&Wl[base] = make_uint2(l0, l1);
        }
        __syncthreads();
#pragma unroll
        for (int ks = 0; ks < 2; ks++) {
            unsigned ah[4][4], al[4][4], bh[4][2], bl[4][2];
#pragma unroll
            for (int mt = 0; mt < 4; mt++) {
                int ba = (wm + mt * 16 + g) * GLD + ks * 8 + qd;
                ah[mt][0] = Ah[ba];
                ah[mt][1] = Ah[ba + 8 * GLD];
                ah[mt][2] = Ah[ba + 4];
                ah[mt][3] = Ah[ba + 8 * GLD + 4];
                al[mt][0] = Al[ba];
                al[mt][1] = Al[ba + 8 * GLD];
                al[mt][2] = Al[ba + 4];
                al[mt][3] = Al[ba + 8 * GLD + 4];
            }
#pragma unroll
            for (int nt = 0; nt < 4; nt++) {
                int bb = (wn + nt * 8 + g) * GLD + ks * 8 + qd;
                bh[nt][0] = Wh[bb];
                bh[nt][1] = Wh[bb + 4];
                bl[nt][0] = Wl[bb];
                bl[nt][1] = Wl[bb + 4];
            }
#pragma unroll
            for (int mt = 0; mt < 4; mt++)
#pragma unroll
                for (int nt = 0; nt < 4; nt++) {
                    mma16(cfr[mt][nt], ah[mt], bh[nt]);
                    mma16(cfr[mt][nt], ah[mt], bl[nt]);
                    mma16(cfr[mt][nt], al[mt], bh[nt]);
                }
        }
    }

#pragma unroll
    for (int mt = 0; mt < 4; mt++) {
        int r0 = bm + wm + mt * 16 + g;
#pragma unroll
        for (int nt = 0; nt < 4; nt++) {
            int col = bn + wn + nt * 8 + qd * 2;
            float2 bb = *(const float2*)(bias + col);
            float2 v0 = make_float2(cfr[mt][nt].x + bb.x, cfr[mt][nt].y + bb.y);
            float2 v1 = make_float2(cfr[mt][nt].z + bb.x, cfr[mt][nt].w + bb.y);
            *(float2*)(C + (size_t)r0 * DD + col) = v0;
            *(float2*)(C + (size_t)(r0 + 8) * DD + col) = v1;
        }
    }
}

__global__ __launch_bounds__(256, 2) void gemm_qkv_kernel(
    const float* __restrict__ x,
    const float* __restrict__ Wq, const float* __restrict__ bq,
    const float* __restrict__ Wk, const float* __restrict__ bk,
    const float* __restrict__ Wv, const float* __restrict__ bv) {
    const float* W; const float* bia; float* C;
    if (blockIdx.z == 0)      { W = Wq; bia = bq; C = g_Q; }
    else if (blockIdx.z == 1) { W = Wk; bia = bk; C = g_K; }
    else                      { W = Wv; bia = bv; C = g_V; }
    gemm_tc_core(x, W, bia, C);
}

__global__ __launch_bounds__(256, 2) void gemm_o_kernel(
    const float* __restrict__ Wo, const float* __restrict__ bo,
    float* __restrict__ out) {
    gemm_tc_core(g_O, Wo, bo, out);
}

// ---------------------------------------------------------------------------
// RoPE over Q and K in-place (unchanged).
// ---------------------------------------------------------------------------
__global__ __launch_bounds__(256) void rope_kernel(const float* __restrict__ freqs) {
    int i = blockIdx.x * blockDim.x + threadIdx.x;
    int dh = i & 511;
    int p  = dh & 31;
    int bs = i >> 9;
    int s  = bs & (SS - 1);
    float4 f = *(const float4*)(freqs + (((size_t)s << 5) + p) * 4);
    float2* qp = (float2*)g_Q + i;
    float2* kp = (float2*)g_K + i;
    float2 qv = *qp;
    float2 kv = *kp;
    float2 qo, ko;
    qo.x = f.x * qv.x + f.y * qv.y;
    qo.y = f.z * qv.x + f.w * qv.y;
    ko.x = f.x * kv.x + f.y * kv.y;
    ko.y = f.z * kv.x + f.w * kv.y;
    *qp = qo;
    *kp = ko;
}

// ---------------------------------------------------------------------------
// Flash attention, bf16 tensor cores with 3xBF16 split.
// Grid (16, 32), 256 threads / 8 warps; warp owns 16 q-rows.
// Smem words (bf16x2): Kh/Kl [64][36] (k-pairs of d), Vth/Vtl [32][72]
// (kv-pairs major, d minor), Ph/Pl [128][36] (kv-pairs of 64-block).
// Ph/Pl double as Q staging before the main loop.
// ---------------------------------------------------------------------------
#define KLD 36
#define VLD 72
#define PLD 36
#define ATT_SMEM_WORDS (2 * 64 * KLD + 2 * 32 * VLD + 2 * 128 * PLD)

__global__ __launch_bounds__(256, 2) void attn_tc_kernel() {
    extern __shared__ unsigned su[];
    unsigned* Kh  = su;
    unsigned* Kl  = Kh + 64 * KLD;
    unsigned* Vth = Kl + 64 * KLD;
    unsigned* Vtl = Vth + 32 * VLD;
    unsigned* Ph  = Vtl + 32 * VLD;
    unsigned* Pl  = Ph + 128 * PLD;

    const int t = threadIdx.x;
    const int lane = t & 31, w = t >> 5;
    const int g = lane >> 2, qd = lane & 3;
    const int qb = blockIdx.x, bh = blockIdx.y;
    const int b = bh >> 4, h = bh & 15;

    const float* Qg = g_Q + ((size_t)b * SS + qb * 128) * DD + h * HD;
    const float* Kg = g_K + (size_t)b * SS * DD + h * HD;
    const float* Vg = g_V + (size_t)b * SS * DD + h * HD;

    // Stage Q (prescaled by scale*log2e) into Ph/Pl as packed hi/lo bf16x2.
    const float qs = ATT_SCALE * LOG2E;
#pragma unroll
    for (int r = 0; r < 8; r++) {
        int idx = r * 256 + t;
        int row = idx >> 4, ch = idx & 15;
        float4 v = *(const float4*)(Qg + (size_t)row * DD + ch * 4);
        unsigned h0, l0, h1, l1;
        split_pair(v.x * qs, v.y * qs, h0, l0);
        split_pair(v.z * qs, v.w * qs, h1, l1);
        int base = row * PLD + ch * 2;
        *(uint2*)&Ph[base] = make_uint2(h0, h1);
        *(uint2*)&Pl[base] = make_uint2(l0, l1);
    }
    __syncthreads();

    // Q fragments (A, m16k16 x 4 k-steps) held in registers for whole kernel.
    unsigned qh[4][4], ql[4][4];
#pragma unroll
    for (int ks = 0; ks < 4; ks++) {
        int ba = (w * 16 + g) * PLD + ks * 8 + qd;
        qh[ks][0] = Ph[ba];
        qh[ks][1] = Ph[ba + 8 * PLD];
        qh[ks][2] = Ph[ba + 4];
        qh[ks][3] = Ph[ba + 8 * PLD + 4];
        ql[ks][0] = Pl[ba];
        ql[ks][1] = Pl[ba + 8 * PLD];
        ql[ks][2] = Pl[ba + 4];
        ql[ks][3] = Pl[ba + 8 * PLD + 4];
    }

    float4 ofr[8];
#pragma unroll
    for (int nt = 0; nt < 8; nt++) ofr[nt] = make_float4(0.f, 0.f, 0.f, 0.f);
    float m0 = -1e30f, m1 = -1e30f, l0a = 0.f, l1a = 0.f;

    for (int kb = 0; kb < SS / 64; kb++) {
        // Prefetch K (row-chunks) and V (2x2 micro-transpose) from gmem.
        float4 kv[4];
        float2 va[4], vb[4];
#pragma unroll
        for (int r = 0; r < 4; r++) {
            int idx = r * 256 + t;
            int row = idx >> 4, ch = idx & 15;
            kv[r] = *(const float4*)(Kg + (size_t)(kb * 64 + row) * DD + ch * 4);
            int j2 = idx >> 5, d2 = idx & 31;
            va[r] = *(const float2*)(Vg + (size_t)(kb * 64 + 2 * j2) * DD + 2 * d2);
            vb[r] = *(const float2*)(Vg + (size_t)(kb * 64 + 2 * j2 + 1) * DD + 2 * d2);
        }
        __syncthreads();   // prev iter's smem reads complete
#pragma unroll
        for (int r = 0; r < 4; r++) {
            int idx = r * 256 + t;
            {
                int row = idx >> 4, ch = idx & 15;
                unsigned h0, l0, h1, l1;
                split_pair(kv[r].x, kv[r].y, h0, l0);
                split_pair(kv[r].z, kv[r].w, h1, l1);
                int base = row * KLD + ch * 2;
                *(uint2*)&Kh[base] = make_uint2(h0, h1);
                *(uint2*)&Kl[base] = make_uint2(l0, l1);
            }
            {
                int j2 = idx >> 5, d2 = idx & 31;
                // word(d) packs V[2j2][d] (low) and V[2j2+1][d] (high)
                unsigned wh0 = pk2(va[r].x, vb[r].x);
                unsigned wh1 = pk2(va[r].y, vb[r].y);
                float r00 = va[r].x - __uint_as_float(wh0 << 16);
                float r10 = vb[r].x - __uint_as_float(wh0 & 0xffff0000u);
                float r01 = va[r].y - __uint_as_float(wh1 << 16);
                float r11 = vb[r].y - __uint_as_float(wh1 & 0xffff0000u);
                unsigned wl0 = pk2(r00, r10);
                unsigned wl1 = pk2(r01, r11);
                int base = j2 * VLD + 2 * d2;
                *(uint2*)&Vth[base] = make_uint2(wh0, wh1);
                *(uint2*)&Vtl[base] = make_uint2(wl0, wl1);
            }
        }
        __syncthreads();

        // S = Q K^T  (log2-domain, pre-scaled)
        float4 sfr[8];
#pragma unroll
        for (int nt = 0; nt < 8; nt++) sfr[nt] = make_float4(0.f, 0.f, 0.f, 0.f);
#pragma unroll
        for (int ks = 0; ks < 4; ks++) {
#pragma unroll
            for (int nt = 0; nt < 8; nt++) {
                int bb = (nt * 8 + g) * KLD + ks * 8 + qd;
                unsigned kbh[2] = { Kh[bb], Kh[bb + 4] };
                unsigned kbl[2] = { Kl[bb], Kl[bb + 4] };
                mma16(sfr[nt], qh[ks], kbh);
                mma16(sfr[nt], qh[ks], kbl);
                mma16(sfr[nt], ql[ks], kbh);
            }
        }

        // Online softmax (rows g and g+8; reduce across quad lanes)
        float rm0 = -1e30f, rm1 = -1e30f;
#pragma unroll
        for (int nt = 0; nt < 8; nt++) {
            rm0 = fmaxf(rm0, fmaxf(sfr[nt].x, sfr[nt].y));
            rm1 = fmaxf(rm1, fmaxf(sfr[nt].z, sfr[nt].w));
        }
        rm0 = fmaxf(rm0, __shfl_xor_sync(0xffffffffu, rm0, 1));
        rm0 = fmaxf(rm0, __shfl_xor_sync(0xffffffffu, rm0, 2));
        rm1 = fmaxf(rm1, __shfl_xor_sync(0xffffffffu, rm1, 1));
        rm1 = fmaxf(rm1, __shfl_xor_sync(0xffffffffu, rm1, 2));
        float mn0 = fmaxf(m0, rm0), mn1 = fmaxf(m1, rm1);
        float a0 = ex2(m0 - mn0), a1 = ex2(m1 - mn1);
        m0 = mn0; m1 = mn1;
        float ps0 = 0.f, ps1 = 0.f;
        const int pr0 = (w * 16 + g) * PLD;
        const int pr1 = pr0 + 8 * PLD;
#pragma unroll
        for (int nt = 0; nt < 8; nt++) {
            float p0 = ex2(sfr[nt].x - mn0);
            float p1 = ex2(sfr[nt].y - mn0);
            float p2 = ex2(sfr[nt].z - mn1);
            float p3 = ex2(sfr[nt].w - mn1);
            ps0 += p0 + p1;
            ps1 += p2 + p3;
            unsigned h01, l01, h23, l23;
            split_pair(p0, p1, h01, l01);
            split_pair(p2, p3, h23, l23);
            int col = nt * 4 + qd;   // kv-pair word index
            Ph[pr0 + col] = h01;
            Pl[pr0 + col] = l01;
            Ph[pr1 + col] = h23;
            Pl[pr1 + col] = l23;
        }
        l0a = l0a * a0 + ps0;
        l1a = l1a * a1 + ps1;
#pragma unroll
        for (int nt = 0; nt < 8; nt++) {
            ofr[nt].x *= a0; ofr[nt].y *= a0;
            ofr[nt].z *= a1; ofr[nt].w *= a1;
        }
        __syncwarp();   // P visible to all lanes of this warp

        // O += P V
#pragma unroll
        for (int ks = 0; ks < 4; ks++) {
            unsigned pah[4], pal[4];
            int ba = (w * 16 + g) * PLD + ks * 8 + qd;
            pah[0] = Ph[ba];
            pah[1] = Ph[ba + 8 * PLD];
            pah[2] = Ph[ba + 4];
            pah[3] = Ph[ba + 8 * PLD + 4];
            pal[0] = Pl[ba];
            pal[1] = Pl[ba + 8 * PLD];
            pal[2] = Pl[ba + 4];
            pal[3] = Pl[ba + 8 * PLD + 4];
#pragma unroll
            for (int nt = 0; nt < 8; nt++) {
                int bb = (ks * 8 + qd) * VLD + nt * 8 + g;
                unsigned vbh[2] = { Vth[bb], Vth[bb + 4 * VLD] };
                unsigned vbl[2] = { Vtl[bb], Vtl[bb + 4 * VLD] };
                mma16(ofr[nt], pah, vbh);
                mma16(ofr[nt], pah, vbl);
                mma16(ofr[nt], pal, vbh);
            }
        }
    }

    // Epilogue: reduce l over quad, normalize, store.
    l0a += __shfl_xor_sync(0xffffffffu, l0a, 1);
    l0a += __shfl_xor_sync(0xffffffffu, l0a, 2);
    l1a += __shfl_xor_sync(0xffffffffu, l1a, 1);
    l1a += __shfl_xor_sync(0xffffffffu, l1a, 2);
    float i0 = 1.f / l0a, i1 = 1.f / l1a;
    float* Og = g_O + ((size_t)b * SS + qb * 128 + w * 16) * DD + h * HD;
#pragma unroll
    for (int nt = 0; nt < 8; nt++) {
        int col = nt * 8 + qd * 2;
        *(float2*)(Og + (size_t)g * DD + col) =
            make_float2(ofr[nt].x * i0, ofr[nt].y * i0);
        *(float2*)(Og + (size_t)(g + 8) * DD + col) =
            make_float2(ofr[nt].z * i1, ofr[nt].w * i1);
    }
}

// ---------------------------------------------------------------------------
extern "C" void kernel_launch(void* const* d_in, const int* in_sizes, int n_in,
                              void* d_out, int out_size) {
    const float* x     = (const float*)d_in[0];
    const float* freqs = (const float*)d_in[1];
    const float* Wq    = (const float*)d_in[2];
    const float* bq    = (const float*)d_in[3];
    const float* Wk    = (const float*)d_in[4];
    const float* bk    = (const float*)d_in[5];
    const float* Wv    = (const float*)d_in[6];
    const float* bv    = (const float*)d_in[7];
    const float* Wo    = (const float*)d_in[8];
    const float* bo    = (const float*)d_in[9];
    float* out = (float*)d_out;

    const size_t gemm_smem = GEMM_SMEM_WORDS * sizeof(unsigned);   // 40960 B
    const size_t attn_smem = ATT_SMEM_WORDS * sizeof(unsigned);    // 73728 B
    cudaFuncSetAttribute(gemm_qkv_kernel, cudaFuncAttributeMaxDynamicSharedMemorySize,
                         (int)gemm_smem);
    cudaFuncSetAttribute(gemm_o_kernel, cudaFuncAttributeMaxDynamicSharedMemorySize,
                         (int)gemm_smem);
    cudaFuncSetAttribute(attn_tc_kernel, cudaFuncAttributeMaxDynamicSharedMemorySize,
                         (int)attn_smem);

    // 1) QKV projections
    gemm_qkv_kernel<<<dim3(DD / 128, (BB * SS) / 128, 3), 256, gemm_smem>>>(
        x, Wq, bq, Wk, bk, Wv, bv);

    // 2) RoPE on Q and K
    rope_kernel<<<(BB * SS * DD / 2) / 256, 256>>>(freqs);

    // 3) Flash attention (bf16 tensor cores, 3x split)
    attn_tc_kernel<<<dim3(SS / 128, BB * HH), 256, attn_smem>>>();

    // 4) Output projection
    gemm_o_kernel<<<dim3(DD / 128, (BB * SS) / 128, 1), 256, gemm_smem>>>(Wo, bo, out);
}